// round 6
// baseline (speedup 1.0000x reference)
#include <cuda_runtime.h>
#include <cstdint>
#include <math.h>

#define T_TOK 16384
#define DIMN  1024
#define HIDN  2048
#define NE    8
#define NA    (2*T_TOK)

#define BK    16
#define PADA  24      // row stride (floats) for 16-float k-tile rows
#define B2STR 264     // ffn2 B smem row stride in floats (132 float2)
#define NSTG  4

// ============================ helpers ============================
#define CP_ASYNC16(dst, src) asm volatile("cp.async.cg.shared.global [%0], [%1], 16;" :: "r"(dst), "l"(src))
#define CP_COMMIT()          asm volatile("cp.async.commit_group;" ::: "memory")
#define CP_WAIT(n)           asm volatile("cp.async.wait_group %0;" :: "n"(n) : "memory")

__device__ __forceinline__ uint32_t smem_u32(const void* p) {
    uint32_t a;
    asm("{ .reg .u64 t; cvta.to.shared.u64 t, %1; cvt.u32.u64 %0, t; }" : "=r"(a) : "l"(p));
    return a;
}
__device__ __forceinline__ float tf32r(float x) {
    uint32_t u; asm("cvt.rna.tf32.f32 %0, %1;" : "=r"(u) : "f"(x)); return __uint_as_float(u);
}
__device__ __forceinline__ void mma_tf32(float* c, const uint32_t* a, const uint32_t* b) {
    asm volatile(
        "mma.sync.aligned.m16n8k8.row.col.f32.tf32.tf32.f32 "
        "{%0,%1,%2,%3}, {%4,%5,%6,%7}, {%8,%9}, {%0,%1,%2,%3};"
        : "+f"(c[0]), "+f"(c[1]), "+f"(c[2]), "+f"(c[3])
        : "r"(a[0]), "r"(a[1]), "r"(a[2]), "r"(a[3]), "r"(b[0]), "r"(b[1]));
}
// k-permutation within each 8-group: pos(k) = (k&~7) | ((k&3)<<1) | ((k>>2)&1)
__device__ __forceinline__ int permk(int k) {
    return (k & ~7) | ((k & 3) << 1) | ((k >> 2) & 1);
}

// ============================ device scratch ============================
__device__ int   g_count[NE];
__device__ int   g_count2[NE];
__device__ int   g_off[NE];
__device__ int   g_choice[T_TOK * 2];
__device__ float g_cw[T_TOK * 2];
__device__ int   g_tokOf[NA];
__device__ float g_wt[NA];
__device__ int   g_slot[T_TOK * 2];
__device__ float g_Xg[(size_t)NA * DIMN];          // gathered tokens, tf32, k-permuted
__device__ float g_Ht[(size_t)NA * HIDN];          // hidden, tf32, k-permuted
__device__ float g_P [(size_t)NA * DIMN];          // per-assignment partials (plain)
__device__ float g_w1t[(size_t)NE * HIDN * DIMN];  // tf32, k-permuted rows
__device__ float g_w3t[(size_t)NE * HIDN * DIMN];
__device__ float g_w2p[(size_t)NE * HIDN * DIMN];  // pairs layout [e][HID/8][4][DIM][2]

// ============================ small kernels ============================
__global__ void reset_kernel() {
    if (threadIdx.x < NE) { g_count[threadIdx.x] = 0; g_count2[threadIdx.x] = 0; }
}

__global__ void gate_kernel(const float* __restrict__ x, const float* __restrict__ wg) {
    int warp = threadIdx.x >> 5, lane = threadIdx.x & 31;
    int t = blockIdx.x * 8 + warp;
    if (t >= T_TOK) return;
    float acc[NE];
#pragma unroll
    for (int e = 0; e < NE; e++) acc[e] = 0.f;
    const float* xr = x + (size_t)t * DIMN;
    for (int d = lane; d < DIMN; d += 32) {
        float xv = xr[d];
#pragma unroll
        for (int e = 0; e < NE; e++) acc[e] += xv * wg[d * NE + e];
    }
#pragma unroll
    for (int e = 0; e < NE; e++)
#pragma unroll
        for (int o = 16; o > 0; o >>= 1) acc[e] += __shfl_xor_sync(0xffffffffu, acc[e], o);
    if (lane == 0) {
        int i0 = 0; float l0 = acc[0];
#pragma unroll
        for (int e = 1; e < NE; e++) if (acc[e] > l0) { l0 = acc[e]; i0 = e; }
        int i1 = -1; float l1 = -3.0e38f;
#pragma unroll
        for (int e = 0; e < NE; e++) if (e != i0 && acc[e] > l1) { l1 = acc[e]; i1 = e; }
        float w0 = 1.f / (1.f + expf(l1 - l0));
        g_choice[2 * t] = i0;  g_choice[2 * t + 1] = i1;
        g_cw[2 * t] = w0;      g_cw[2 * t + 1] = 1.f - w0;
        atomicAdd(&g_count[i0], 1);
        atomicAdd(&g_count[i1], 1);
    }
}

__global__ void scan_kernel() {
    if (threadIdx.x == 0) {
        int off = 0;
        for (int e = 0; e < NE; e++) { g_off[e] = off; off += g_count[e]; }
    }
}

__global__ void build_kernel() {
    int t = blockIdx.x * blockDim.x + threadIdx.x;
    if (t >= T_TOK) return;
#pragma unroll
    for (int j = 0; j < 2; j++) {
        int e = g_choice[2 * t + j];
        int p = atomicAdd(&g_count2[e], 1);
        int s = g_off[e] + p;
        g_tokOf[s] = t;
        g_wt[s] = g_cw[2 * t + j];
        g_slot[2 * t + j] = s;
    }
}

// gather + tf32 round + k-permute (per thread: one 8-group)
__global__ void gather_kernel(const float* __restrict__ x) {
    size_t idx = (size_t)blockIdx.x * blockDim.x + threadIdx.x;
    if (idx >= (size_t)NA * (DIMN / 8)) return;
    int row = (int)(idx / (DIMN / 8));
    int g = (int)(idx % (DIMN / 8)) * 8;
    int tok = g_tokOf[row];
    const float* sp = &x[(size_t)tok * DIMN + g];
    float4 v0 = *reinterpret_cast<const float4*>(sp);
    float4 v1 = *reinterpret_cast<const float4*>(sp + 4);
    float4 lo, hi;   // perm order: k 0,4,1,5 | 2,6,3,7
    lo.x = tf32r(v0.x); lo.y = tf32r(v1.x); lo.z = tf32r(v0.y); lo.w = tf32r(v1.y);
    hi.x = tf32r(v0.z); hi.y = tf32r(v1.z); hi.z = tf32r(v0.w); hi.w = tf32r(v1.w);
    float* dp = &g_Xg[(size_t)row * DIMN + g];
    *reinterpret_cast<float4*>(dp) = lo;
    *reinterpret_cast<float4*>(dp + 4) = hi;
}

// w1/w3: tf32 round + k-permute (per thread: one 8-group)
__global__ void convw13_kernel(const float* __restrict__ w1, const float* __restrict__ w3) {
    size_t idx = (size_t)blockIdx.x * blockDim.x + threadIdx.x;
    if (idx >= (size_t)NE * HIDN * DIMN / 8) return;
    size_t o = idx * 8;
    {
        float4 v0 = *reinterpret_cast<const float4*>(&w1[o]);
        float4 v1 = *reinterpret_cast<const float4*>(&w1[o + 4]);
        float4 lo, hi;
        lo.x = tf32r(v0.x); lo.y = tf32r(v1.x); lo.z = tf32r(v0.y); lo.w = tf32r(v1.y);
        hi.x = tf32r(v0.z); hi.y = tf32r(v1.z); hi.z = tf32r(v0.w); hi.w = tf32r(v1.w);
        *reinterpret_cast<float4*>(&g_w1t[o]) = lo;
        *reinterpret_cast<float4*>(&g_w1t[o + 4]) = hi;
    }
    {
        float4 v0 = *reinterpret_cast<const float4*>(&w3[o]);
        float4 v1 = *reinterpret_cast<const float4*>(&w3[o + 4]);
        float4 lo, hi;
        lo.x = tf32r(v0.x); lo.y = tf32r(v1.x); lo.z = tf32r(v0.y); lo.w = tf32r(v1.y);
        hi.x = tf32r(v0.z); hi.y = tf32r(v1.z); hi.z = tf32r(v0.w); hi.w = tf32r(v1.w);
        *reinterpret_cast<float4*>(&g_w3t[o]) = lo;
        *reinterpret_cast<float4*>(&g_w3t[o + 4]) = hi;
    }
}

// w2 -> pairs layout: g_w2p[((e*(HID/8)+kg)*4+klo)*DIM + n] (float2) =
//   ( w2[e][kg*8+klo][n], w2[e][kg*8+klo+4][n] ), tf32-rounded
__global__ void convw2p_kernel(const float* __restrict__ w2) {
    size_t idx = (size_t)blockIdx.x * blockDim.x + threadIdx.x;
    if (idx >= (size_t)NE * (HIDN / 2) * DIMN) return;
    int n = (int)(idx % DIMN);
    size_t rest = idx / DIMN;
    int klo = (int)(rest & 3);
    size_t rest2 = rest >> 2;
    int kg = (int)(rest2 % (HIDN / 8));
    int e = (int)(rest2 / (HIDN / 8));
    size_t srow = ((size_t)e * HIDN + kg * 8 + klo) * DIMN + n;
    float a = tf32r(w2[srow]);
    float b = tf32r(w2[srow + 4 * DIMN]);
    float* dp = &g_w2p[idx * 2];
    dp[0] = a; dp[1] = b;
}

// ============================ ffn1: H = silu(Xg W1^T) * (Xg W3^T) ============================
// BM=128 BN=64 BK=16. 256 threads, 8 warps as 4(m) x 2(n); warp 32x32 (dual output).
__global__ void __launch_bounds__(256, 2) ffn1_kernel() {
    int e = blockIdx.z;
    int cnt = g_count[e];
    int mb = blockIdx.y;
    if (mb * 128 >= cnt) return;
    int base = g_off[e] + mb * 128;
    int n0 = blockIdx.x * 64;

    extern __shared__ float smem[];
    float* As  = smem;                       // [NSTG][128*PADA]
    float* B1s = As  + NSTG * 128 * PADA;    // [NSTG][64*PADA]
    float* B3s = B1s + NSTG * 64 * PADA;     // [NSTG][64*PADA]
    const int A_STG = 128 * PADA, B_STG = 64 * PADA;

    int tid = threadIdx.x, wid = tid >> 5, lane = tid & 31;
    int wm = wid & 3, wn = wid >> 2;

    // loaders
    int arowL = tid >> 1, apart = tid & 1;   // A: row, 8-float half
    int arow = base + arowL; if (arow >= NA) arow = NA - 1;
    const float* srcA0 = g_Xg + (size_t)arow * DIMN + apart * 8;
    uint32_t dstA0 = smem_u32(&As[arowL * PADA + apart * 8]);

    int browL = tid >> 2, bchk = tid & 3;    // B: row, 4-float chunk
    const float* srcB10 = g_w1t + ((size_t)e * HIDN + n0 + browL) * DIMN + bchk * 4;
    const float* srcB30 = g_w3t + ((size_t)e * HIDN + n0 + browL) * DIMN + bchk * 4;
    uint32_t dstB10 = smem_u32(&B1s[browL * PADA + bchk * 4]);
    uint32_t dstB30 = smem_u32(&B3s[browL * PADA + bchk * 4]);

    float acc1[2][4][4], acc3[2][4][4];
#pragma unroll
    for (int i = 0; i < 2; i++)
#pragma unroll
        for (int j = 0; j < 4; j++)
#pragma unroll
            for (int v = 0; v < 4; v++) { acc1[i][j][v] = 0.f; acc3[i][j][v] = 0.f; }

    const int KT = DIMN / BK;   // 64
    auto issue = [&](int s, int kc) {
        uint32_t aoff = (uint32_t)(s * A_STG * 4);
        uint32_t boff = (uint32_t)(s * B_STG * 4);
        const float* sa = srcA0 + kc * BK;
        CP_ASYNC16(dstA0 + aoff, sa); CP_ASYNC16(dstA0 + aoff + 16, sa + 4);
        CP_ASYNC16(dstB10 + boff, srcB10 + kc * BK);
        CP_ASYNC16(dstB30 + boff, srcB30 + kc * BK);
        CP_COMMIT();
    };
    issue(0, 0); issue(1, 1); issue(2, 2);

    for (int kt = 0; kt < KT; kt++) {
        int pf = kt + 3;
        issue(pf & 3, pf < KT ? pf : KT - 1);
        CP_WAIT(3);
        __syncthreads();

        const float* A  = As  + (kt & 3) * A_STG;
        const float* B1 = B1s + (kt & 3) * B_STG;
        const float* B3 = B3s + (kt & 3) * B_STG;
        int klo2 = (lane & 3) * 2;
#pragma unroll
        for (int kk = 0; kk < 2; kk++) {
            int koff = kk * 8 + klo2;
            uint32_t a[2][4];
#pragma unroll
            for (int i = 0; i < 2; i++) {
                int r = wm * 32 + i * 16 + (lane >> 2);
                float2 p0 = *reinterpret_cast<const float2*>(&A[r * PADA + koff]);
                float2 p1 = *reinterpret_cast<const float2*>(&A[(r + 8) * PADA + koff]);
                a[i][0] = __float_as_uint(p0.x); a[i][1] = __float_as_uint(p1.x);
                a[i][2] = __float_as_uint(p0.y); a[i][3] = __float_as_uint(p1.y);
            }
            uint32_t b1[4][2], b3[4][2];
#pragma unroll
            for (int j = 0; j < 4; j++) {
                int n = wn * 32 + j * 8 + (lane >> 2);
                float2 q1 = *reinterpret_cast<const float2*>(&B1[n * PADA + koff]);
                float2 q3 = *reinterpret_cast<const float2*>(&B3[n * PADA + koff]);
                b1[j][0] = __float_as_uint(q1.x); b1[j][1] = __float_as_uint(q1.y);
                b3[j][0] = __float_as_uint(q3.x); b3[j][1] = __float_as_uint(q3.y);
            }
#pragma unroll
            for (int i = 0; i < 2; i++)
#pragma unroll
                for (int j = 0; j < 4; j++) {
                    mma_tf32(acc1[i][j], a[i], b1[j]);
                    mma_tf32(acc3[i][j], a[i], b3[j]);
                }
        }
        __syncthreads();
    }

    // epilogue: h = silu(z1)*z3, tf32-round, store to k-permuted Ht
#pragma unroll
    for (int i = 0; i < 2; i++) {
#pragma unroll
        for (int half = 0; half < 2; half++) {
            int rloc = wm * 32 + i * 16 + (lane >> 2) + half * 8;
            if (mb * 128 + rloc < cnt) {
                float* hrow = g_Ht + (size_t)(base + rloc) * HIDN + n0;
#pragma unroll
                for (int j = 0; j < 4; j++) {
                    int cl = wn * 32 + j * 8 + (lane & 3) * 2;
                    float z0 = acc1[i][j][half * 2 + 0];
                    float z1 = acc1[i][j][half * 2 + 1];
                    float h0 = tf32r(z0 / (1.f + __expf(-z0)) * acc3[i][j][half * 2 + 0]);
                    float h1 = tf32r(z1 / (1.f + __expf(-z1)) * acc3[i][j][half * 2 + 1]);
                    hrow[permk(cl)]     = h0;
                    hrow[permk(cl + 1)] = h1;
                }
            }
        }
    }
}

// ============================ ffn2: P = H W2 ============================
// BM=128 BN=128 BK=16. 256 threads, 8 warps as 4(m) x 2(n); warp 32x64.
__global__ void __launch_bounds__(256, 2) ffn2_kernel() {
    int e = blockIdx.z;
    int cnt = g_count[e];
    int mb = blockIdx.y;
    if (mb * 128 >= cnt) return;
    int base = g_off[e] + mb * 128;
    int n0 = blockIdx.x * 128;

    extern __shared__ float smem[];
    float* As = smem;                        // [NSTG][128*PADA]
    float* Bs = As + NSTG * 128 * PADA;      // [NSTG][8*B2STR]
    const int A_STG = 128 * PADA, B_STG = 8 * B2STR;

    int tid = threadIdx.x, wid = tid >> 5, lane = tid & 31;
    int wm = wid & 3, wn = wid >> 2;

    int arowL = tid >> 1, apart = tid & 1;
    int arow = base + arowL; if (arow >= NA) arow = NA - 1;
    const float* srcA0 = g_Ht + (size_t)arow * HIDN + apart * 8;
    uint32_t dstA0 = smem_u32(&As[arowL * PADA + apart * 8]);

    // B loader: 8 pair-rows x 128 float2 per stage; 32 threads/row, 8 floats each
    int brow = tid >> 5;                 // 0..7  (kk = brow>>2, klo = brow&3)
    int bcol = (tid & 31) * 8;           // float offset within row (2 chunks)
    const float* srcB0 = g_w2p +
        ((((size_t)e * (HIDN / 8) + (brow >> 2)) * 4 + (brow & 3)) * DIMN + n0) * 2 + bcol;
    uint32_t dstB0 = smem_u32(&Bs[brow * B2STR + bcol]);
    const size_t bstep = (size_t)2 * 4 * DIMN * 2;   // advance kg by 2 per kt (floats)

    float acc[2][8][4];
#pragma unroll
    for (int i = 0; i < 2; i++)
#pragma unroll
        for (int j = 0; j < 8; j++)
#pragma unroll
            for (int v = 0; v < 4; v++) acc[i][j][v] = 0.f;

    const int KT = HIDN / BK;   // 128
    auto issue = [&](int s, int kc) {
        uint32_t aoff = (uint32_t)(s * A_STG * 4);
        uint32_t boff = (uint32_t)(s * B_STG * 4);
        const float* sa = srcA0 + kc * BK;
        CP_ASYNC16(dstA0 + aoff, sa); CP_ASYNC16(dstA0 + aoff + 16, sa + 4);
        const float* sb = srcB0 + (size_t)kc * bstep;
        CP_ASYNC16(dstB0 + boff, sb); CP_ASYNC16(dstB0 + boff + 16, sb + 4);
        CP_COMMIT();
    };
    issue(0, 0); issue(1, 1); issue(2, 2);

    for (int kt = 0; kt < KT; kt++) {
        int pf = kt + 3;
        issue(pf & 3, pf < KT ? pf : KT - 1);
        CP_WAIT(3);
        __syncthreads();

        const float* A = As + (kt & 3) * A_STG;
        const float* B = Bs + (kt & 3) * B_STG;
        int klo = lane & 3;
#pragma unroll
        for (int kk = 0; kk < 2; kk++) {
            uint32_t a[2][4];
            int koff = kk * 8 + klo * 2;
#pragma unroll
            for (int i = 0; i < 2; i++) {
                int r = wm * 32 + i * 16 + (lane >> 2);
                float2 p0 = *reinterpret_cast<const float2*>(&A[r * PADA + koff]);
                float2 p1 = *reinterpret_cast<const float2*>(&A[(r + 8) * PADA + koff]);
                a[i][0] = __float_as_uint(p0.x); a[i][1] = __float_as_uint(p1.x);
                a[i][2] = __float_as_uint(p0.y); a[i][3] = __float_as_uint(p1.y);
            }
            uint32_t b[8][2];
            int brow2 = kk * 4 + klo;
#pragma unroll
            for (int j = 0; j < 8; j++) {
                int n = wn * 64 + j * 8 + (lane >> 2);
                float2 q = *reinterpret_cast<const float2*>(&B[brow2 * B2STR + n * 2]);
                b[j][0] = __float_as_uint(q.x); b[j][1] = __float_as_uint(q.y);
            }
#pragma unroll
            for (int i = 0; i < 2; i++)
#pragma unroll
                for (int j = 0; j < 8; j++)
                    mma_tf32(acc[i][j], a[i], b[j]);
        }
        __syncthreads();
    }

#pragma unroll
    for (int i = 0; i < 2; i++) {
#pragma unroll
        for (int half = 0; half < 2; half++) {
            int rloc = wm * 32 + i * 16 + (lane >> 2) + half * 8;
            if (mb * 128 + rloc < cnt) {
                float* prow = g_P + (size_t)(base + rloc) * DIMN + n0;
#pragma unroll
                for (int j = 0; j < 8; j++) {
                    int cl = wn * 64 + j * 8 + (lane & 3) * 2;
                    *reinterpret_cast<float2*>(&prow[cl]) =
                        make_float2(acc[i][j][half * 2 + 0], acc[i][j][half * 2 + 1]);
                }
            }
        }
    }
}

// ============================ combine ============================
__global__ void combine_kernel(float* __restrict__ y) {
    size_t idx = (size_t)blockIdx.x * blockDim.x + threadIdx.x;
    if (idx >= (size_t)T_TOK * DIMN / 4) return;
    int t = (int)(idx / (DIMN / 4));
    int d4 = (int)(idx % (DIMN / 4)) * 4;
    int s0 = g_slot[2 * t], s1 = g_slot[2 * t + 1];
    float w0 = g_wt[s0], w1 = g_wt[s1];
    float4 p0 = *reinterpret_cast<const float4*>(&g_P[(size_t)s0 * DIMN + d4]);
    float4 p1 = *reinterpret_cast<const float4*>(&g_P[(size_t)s1 * DIMN + d4]);
    float4 r;
    r.x = w0 * p0.x + w1 * p1.x;
    r.y = w0 * p0.y + w1 * p1.y;
    r.z = w0 * p0.z + w1 * p1.z;
    r.w = w0 * p0.w + w1 * p1.w;
    *reinterpret_cast<float4*>(&y[(size_t)t * DIMN + d4]) = r;
}

// ============================ launch ============================
extern "C" void kernel_launch(void* const* d_in, const int* in_sizes, int n_in,
                              void* d_out, int out_size) {
    const float* x  = (const float*)d_in[0];
    const float* wg = (const float*)d_in[1];
    const float* w1 = (const float*)d_in[2];
    const float* w2 = (const float*)d_in[3];
    const float* w3 = (const float*)d_in[4];
    float* y = (float*)d_out;

    const int smem1 = NSTG * (128 + 64 + 64) * PADA * 4;      // 98304
    const int smem2 = NSTG * (128 * PADA + 8 * B2STR) * 4;    // 82944
    cudaFuncSetAttribute(ffn1_kernel, cudaFuncAttributeMaxDynamicSharedMemorySize, smem1);
    cudaFuncSetAttribute(ffn2_kernel, cudaFuncAttributeMaxDynamicSharedMemorySize, smem2);

    reset_kernel<<<1, 32>>>();
    gate_kernel<<<T_TOK / 8, 256>>>(x, wg);
    scan_kernel<<<1, 32>>>();
    build_kernel<<<T_TOK / 256, 256>>>();
    gather_kernel<<<(int)(((size_t)NA * (DIMN / 8) + 255) / 256), 256>>>(x);
    convw13_kernel<<<(int)(((size_t)NE * HIDN * DIMN / 8 + 255) / 256), 256>>>(w1, w3);
    convw2p_kernel<<<(int)(((size_t)NE * (HIDN / 2) * DIMN + 255) / 256), 256>>>(w2);
    ffn1_kernel<<<dim3(HIDN / 64, 128, NE), 256, smem1>>>();
    ffn2_kernel<<<dim3(DIMN / 128, 128, NE), 256, smem2>>>();
    combine_kernel<<<(T_TOK * DIMN / 4 + 255) / 256, 256>>>(y);
}

// round 7
// speedup vs baseline: 1.0440x; 1.0440x over previous
#include <cuda_runtime.h>
#include <cstdint>
#include <math.h>

#define T_TOK 16384
#define DIMN  1024
#define HIDN  2048
#define NE    8
#define NA    (2*T_TOK)

#define BK    16
#define PADA  20    // row stride (floats) for A / NT-B tiles
#define PADB  136   // row stride (floats) for ffn2 B tile [16][128]
#define NSTG  3

// ============================ helpers ============================
#define CP_ASYNC16(dst, src) asm volatile("cp.async.cg.shared.global [%0], [%1], 16;" :: "r"(dst), "l"(src))
#define CP_COMMIT()          asm volatile("cp.async.commit_group;" ::: "memory")
#define CP_WAIT(n)           asm volatile("cp.async.wait_group %0;" :: "n"(n) : "memory")

__device__ __forceinline__ uint32_t smem_u32(const void* p) {
    uint32_t a;
    asm("{ .reg .u64 t; cvta.to.shared.u64 t, %1; cvt.u32.u64 %0, t; }" : "=r"(a) : "l"(p));
    return a;
}
__device__ __forceinline__ float tf32r(float x) {
    uint32_t u; asm("cvt.rna.tf32.f32 %0, %1;" : "=r"(u) : "f"(x)); return __uint_as_float(u);
}
__device__ __forceinline__ void mma_tf32(float* c, const uint32_t* a, const uint32_t* b) {
    asm volatile(
        "mma.sync.aligned.m16n8k8.row.col.f32.tf32.tf32.f32 "
        "{%0,%1,%2,%3}, {%4,%5,%6,%7}, {%8,%9}, {%0,%1,%2,%3};"
        : "+f"(c[0]), "+f"(c[1]), "+f"(c[2]), "+f"(c[3])
        : "r"(a[0]), "r"(a[1]), "r"(a[2]), "r"(a[3]), "r"(b[0]), "r"(b[1]));
}

// ============================ device scratch ============================
__device__ int   g_count[NE];
__device__ int   g_count2[NE];
__device__ int   g_off[NE];
__device__ int   g_choice[T_TOK * 2];
__device__ float g_cw[T_TOK * 2];
__device__ int   g_tokOf[NA];
__device__ float g_wt[NA];
__device__ int   g_slot[T_TOK * 2];
__device__ float g_Xg[(size_t)NA * DIMN];          // gathered tokens, tf32-rounded
__device__ float g_Ht[(size_t)NA * HIDN];          // hidden, tf32-rounded
__device__ float g_P [(size_t)NA * DIMN];          // per-assignment partials
__device__ float g_w1t[(size_t)NE * HIDN * DIMN];  // tf32-rounded
__device__ float g_w3t[(size_t)NE * HIDN * DIMN];
__device__ float g_w2r[(size_t)NE * HIDN * DIMN];  // tf32-rounded (same layout as w2)

// ============================ small kernels ============================
__global__ void reset_kernel() {
    if (threadIdx.x < NE) { g_count[threadIdx.x] = 0; g_count2[threadIdx.x] = 0; }
}

__global__ void gate_kernel(const float* __restrict__ x, const float* __restrict__ wg) {
    int warp = threadIdx.x >> 5, lane = threadIdx.x & 31;
    int t = blockIdx.x * 8 + warp;
    if (t >= T_TOK) return;
    float acc[NE];
#pragma unroll
    for (int e = 0; e < NE; e++) acc[e] = 0.f;
    const float* xr = x + (size_t)t * DIMN;
    for (int d = lane; d < DIMN; d += 32) {
        float xv = xr[d];
#pragma unroll
        for (int e = 0; e < NE; e++) acc[e] += xv * wg[d * NE + e];
    }
#pragma unroll
    for (int e = 0; e < NE; e++)
#pragma unroll
        for (int o = 16; o > 0; o >>= 1) acc[e] += __shfl_xor_sync(0xffffffffu, acc[e], o);
    if (lane == 0) {
        int i0 = 0; float l0 = acc[0];
#pragma unroll
        for (int e = 1; e < NE; e++) if (acc[e] > l0) { l0 = acc[e]; i0 = e; }
        int i1 = -1; float l1 = -3.0e38f;
#pragma unroll
        for (int e = 0; e < NE; e++) if (e != i0 && acc[e] > l1) { l1 = acc[e]; i1 = e; }
        float w0 = 1.f / (1.f + expf(l1 - l0));
        g_choice[2 * t] = i0;  g_choice[2 * t + 1] = i1;
        g_cw[2 * t] = w0;      g_cw[2 * t + 1] = 1.f - w0;
        atomicAdd(&g_count[i0], 1);
        atomicAdd(&g_count[i1], 1);
    }
}

__global__ void scan_kernel() {
    if (threadIdx.x == 0) {
        int off = 0;
        for (int e = 0; e < NE; e++) { g_off[e] = off; off += g_count[e]; }
    }
}

__global__ void build_kernel() {
    int t = blockIdx.x * blockDim.x + threadIdx.x;
    if (t >= T_TOK) return;
#pragma unroll
    for (int j = 0; j < 2; j++) {
        int e = g_choice[2 * t + j];
        int p = atomicAdd(&g_count2[e], 1);
        int s = g_off[e] + p;
        g_tokOf[s] = t;
        g_wt[s] = g_cw[2 * t + j];
        g_slot[2 * t + j] = s;
    }
}

__global__ void gather_kernel(const float* __restrict__ x) {
    size_t idx = (size_t)blockIdx.x * blockDim.x + threadIdx.x;
    if (idx >= (size_t)NA * (DIMN / 4)) return;
    int row = (int)(idx / (DIMN / 4));
    int c4 = (int)(idx % (DIMN / 4)) * 4;
    int tok = g_tokOf[row];
    float4 v = *reinterpret_cast<const float4*>(&x[(size_t)tok * DIMN + c4]);
    v.x = tf32r(v.x); v.y = tf32r(v.y); v.z = tf32r(v.z); v.w = tf32r(v.w);
    *reinterpret_cast<float4*>(&g_Xg[(size_t)row * DIMN + c4]) = v;
}

__global__ void convw_kernel(const float* __restrict__ w1, const float* __restrict__ w2,
                             const float* __restrict__ w3) {
    size_t idx = (size_t)blockIdx.x * blockDim.x + threadIdx.x;
    if (idx >= (size_t)NE * HIDN * DIMN / 4) return;
    size_t o = idx * 4;
    float4 a = *reinterpret_cast<const float4*>(&w1[o]);
    a.x = tf32r(a.x); a.y = tf32r(a.y); a.z = tf32r(a.z); a.w = tf32r(a.w);
    *reinterpret_cast<float4*>(&g_w1t[o]) = a;
    float4 b = *reinterpret_cast<const float4*>(&w3[o]);
    b.x = tf32r(b.x); b.y = tf32r(b.y); b.z = tf32r(b.z); b.w = tf32r(b.w);
    *reinterpret_cast<float4*>(&g_w3t[o]) = b;
    float4 c = *reinterpret_cast<const float4*>(&w2[o]);
    c.x = tf32r(c.x); c.y = tf32r(c.y); c.z = tf32r(c.z); c.w = tf32r(c.w);
    *reinterpret_cast<float4*>(&g_w2r[o]) = c;
}

// ============================ ffn1: H = silu(Xg W1^T) * (Xg W3^T) ============================
// BM=128 BN=64 BK=16. 256 threads, 8 warps as 4(m) x 2(n); warp tile 32x32 (dual output).
// 3-stage cp.async ring, single __syncthreads per k-iteration.
__global__ void __launch_bounds__(256, 2) ffn1_kernel() {
    int e = blockIdx.z;
    int cnt = g_count[e];
    int mb = blockIdx.y;
    if (mb * 128 >= cnt) return;
    int base = g_off[e] + mb * 128;
    int n0 = blockIdx.x * 64;

    extern __shared__ float smem[];
    float* As  = smem;                       // [NSTG][128*PADA]
    float* B1s = As  + NSTG * 128 * PADA;    // [NSTG][64*PADA]
    float* B3s = B1s + NSTG * 64 * PADA;     // [NSTG][64*PADA]
    const int A_STG = 128 * PADA, B_STG = 64 * PADA;

    int tid = threadIdx.x, wid = tid >> 5, lane = tid & 31;
    int wm = wid & 3, wn = wid >> 2;

    // A tile loads: row = tid>>1, col base = (tid&1)*8; 16B chunks at +0, +4 floats
    int arowL = tid >> 1;
    int acol = (tid & 1) * 8;
    int arow = base + arowL; if (arow >= NA) arow = NA - 1;
    const float* srcA0 = g_Xg + (size_t)arow * DIMN + acol;
    uint32_t dstA0 = smem_u32(&As[arowL * PADA + acol]);

    int browL = tid >> 2;
    int bcol = (tid & 3) * 4;
    const float* srcB10 = g_w1t + ((size_t)e * HIDN + n0 + browL) * DIMN + bcol;
    const float* srcB30 = g_w3t + ((size_t)e * HIDN + n0 + browL) * DIMN + bcol;
    uint32_t dstB10 = smem_u32(&B1s[browL * PADA + bcol]);
    uint32_t dstB30 = smem_u32(&B3s[browL * PADA + bcol]);

    float acc1[2][4][4], acc3[2][4][4];
#pragma unroll
    for (int i = 0; i < 2; i++)
#pragma unroll
        for (int j = 0; j < 4; j++)
#pragma unroll
            for (int v = 0; v < 4; v++) { acc1[i][j][v] = 0.f; acc3[i][j][v] = 0.f; }

    auto issue = [&](int s, int kc) {
        uint32_t aoff = (uint32_t)(s * A_STG * 4);
        uint32_t boff = (uint32_t)(s * B_STG * 4);
        const float* sa = srcA0 + kc * BK;
        CP_ASYNC16(dstA0 + aoff, sa); CP_ASYNC16(dstA0 + aoff + 16, sa + 4);
        CP_ASYNC16(dstB10 + boff, srcB10 + kc * BK);
        CP_ASYNC16(dstB30 + boff, srcB30 + kc * BK);
        CP_COMMIT();
    };

    const int KT = DIMN / BK;   // 64
    issue(0, 0); issue(1, 1);

    int stg = 0;
    for (int kt = 0; kt < KT; kt++) {
        CP_WAIT(1);
        __syncthreads();
        if (kt + 2 < KT) {
            int s = stg + 2; if (s >= NSTG) s -= NSTG;
            issue(s, kt + 2);
        }

        const float* A  = As  + stg * A_STG;
        const float* B1 = B1s + stg * B_STG;
        const float* B3 = B3s + stg * B_STG;
#pragma unroll
        for (int kk = 0; kk < 2; kk++) {
            int k0 = kk * 8;
            uint32_t a[2][4];
#pragma unroll
            for (int i = 0; i < 2; i++) {
                int r = wm * 32 + i * 16 + (lane >> 2);
                int c = k0 + (lane & 3);
                a[i][0] = __float_as_uint(A[r * PADA + c]);
                a[i][1] = __float_as_uint(A[(r + 8) * PADA + c]);
                a[i][2] = __float_as_uint(A[r * PADA + c + 4]);
                a[i][3] = __float_as_uint(A[(r + 8) * PADA + c + 4]);
            }
            uint32_t b1[4][2], b3[4][2];
#pragma unroll
            for (int j = 0; j < 4; j++) {
                int n = wn * 32 + j * 8 + (lane >> 2);
                int c = k0 + (lane & 3);
                b1[j][0] = __float_as_uint(B1[n * PADA + c]);
                b1[j][1] = __float_as_uint(B1[n * PADA + c + 4]);
                b3[j][0] = __float_as_uint(B3[n * PADA + c]);
                b3[j][1] = __float_as_uint(B3[n * PADA + c + 4]);
            }
#pragma unroll
            for (int i = 0; i < 2; i++)
#pragma unroll
                for (int j = 0; j < 4; j++) {
                    mma_tf32(acc1[i][j], a[i], b1[j]);
                    mma_tf32(acc3[i][j], a[i], b3[j]);
                }
        }
        if (++stg >= NSTG) stg = 0;
    }
    CP_WAIT(0);

    // epilogue: h = silu(z1)*z3, tf32-round, store
#pragma unroll
    for (int i = 0; i < 2; i++) {
#pragma unroll
        for (int half = 0; half < 2; half++) {
            int rloc = wm * 32 + i * 16 + (lane >> 2) + half * 8;
            if (mb * 128 + rloc < cnt) {
                float* hrow = g_Ht + (size_t)(base + rloc) * HIDN + n0;
#pragma unroll
                for (int j = 0; j < 4; j++) {
                    int cl = wn * 32 + j * 8 + (lane & 3) * 2;
                    float z0 = acc1[i][j][half * 2 + 0];
                    float z1 = acc1[i][j][half * 2 + 1];
                    float h0 = tf32r(z0 / (1.f + __expf(-z0)) * acc3[i][j][half * 2 + 0]);
                    float h1 = tf32r(z1 / (1.f + __expf(-z1)) * acc3[i][j][half * 2 + 1]);
                    *reinterpret_cast<float2*>(&hrow[cl]) = make_float2(h0, h1);
                }
            }
        }
    }
}

// ============================ ffn2: P = H W2 ============================
// BM=128 BN=128 BK=16. 256 threads, 8 warps as 4(m) x 2(n); warp tile 32x64.
__global__ void __launch_bounds__(256, 2) ffn2_kernel() {
    int e = blockIdx.z;
    int cnt = g_count[e];
    int mb = blockIdx.y;
    if (mb * 128 >= cnt) return;
    int base = g_off[e] + mb * 128;
    int n0 = blockIdx.x * 128;

    extern __shared__ float smem[];
    float* As = smem;                        // [NSTG][128*PADA]
    float* Bs = As + NSTG * 128 * PADA;      // [NSTG][16*PADB]
    const int A_STG = 128 * PADA, B_STG = 16 * PADB;

    int tid = threadIdx.x, wid = tid >> 5, lane = tid & 31;
    int wm = wid & 3, wn = wid >> 2;

    int arowL = tid >> 1;
    int acol = (tid & 1) * 8;
    int arow = base + arowL; if (arow >= NA) arow = NA - 1;
    const float* srcA0 = g_Ht + (size_t)arow * HIDN + acol;
    uint32_t dstA0 = smem_u32(&As[arowL * PADA + acol]);

    int browL = tid >> 4;
    int bcol = (tid & 15) * 8;
    const float* srcB0 = g_w2r + ((size_t)e * HIDN + browL) * DIMN + n0 + bcol;
    uint32_t dstB0 = smem_u32(&Bs[browL * PADB + bcol]);

    float acc[2][8][4];
#pragma unroll
    for (int i = 0; i < 2; i++)
#pragma unroll
        for (int j = 0; j < 8; j++)
#pragma unroll
            for (int v = 0; v < 4; v++) acc[i][j][v] = 0.f;

    auto issue = [&](int s, int kc) {
        uint32_t aoff = (uint32_t)(s * A_STG * 4);
        uint32_t boff = (uint32_t)(s * B_STG * 4);
        const float* sa = srcA0 + kc * BK;
        CP_ASYNC16(dstA0 + aoff, sa); CP_ASYNC16(dstA0 + aoff + 16, sa + 4);
        const float* sb = srcB0 + (size_t)kc * BK * DIMN;
        CP_ASYNC16(dstB0 + boff, sb); CP_ASYNC16(dstB0 + boff + 16, sb + 4);
        CP_COMMIT();
    };

    const int KT = HIDN / BK;   // 128
    issue(0, 0); issue(1, 1);

    int stg = 0;
    for (int kt = 0; kt < KT; kt++) {
        CP_WAIT(1);
        __syncthreads();
        if (kt + 2 < KT) {
            int s = stg + 2; if (s >= NSTG) s -= NSTG;
            issue(s, kt + 2);
        }

        const float* A = As + stg * A_STG;
        const float* B = Bs + stg * B_STG;
#pragma unroll
        for (int kk = 0; kk < 2; kk++) {
            int k0 = kk * 8;
            uint32_t a[2][4];
#pragma unroll
            for (int i = 0; i < 2; i++) {
                int r = wm * 32 + i * 16 + (lane >> 2);
                int c = k0 + (lane & 3);
                a[i][0] = __float_as_uint(A[r * PADA + c]);
                a[i][1] = __float_as_uint(A[(r + 8) * PADA + c]);
                a[i][2] = __float_as_uint(A[r * PADA + c + 4]);
                a[i][3] = __float_as_uint(A[(r + 8) * PADA + c + 4]);
            }
            uint32_t b[8][2];
#pragma unroll
            for (int j = 0; j < 8; j++) {
                int n = wn * 64 + j * 8 + (lane >> 2);
                int k = k0 + (lane & 3);
                b[j][0] = __float_as_uint(B[k * PADB + n]);
                b[j][1] = __float_as_uint(B[(k + 4) * PADB + n]);
            }
#pragma unroll
            for (int i = 0; i < 2; i++)
#pragma unroll
                for (int j = 0; j < 8; j++)
                    mma_tf32(acc[i][j], a[i], b[j]);
        }
        if (++stg >= NSTG) stg = 0;
    }
    CP_WAIT(0);

#pragma unroll
    for (int i = 0; i < 2; i++) {
#pragma unroll
        for (int half = 0; half < 2; half++) {
            int rloc = wm * 32 + i * 16 + (lane >> 2) + half * 8;
            if (mb * 128 + rloc < cnt) {
                float* prow = g_P + (size_t)(base + rloc) * DIMN + n0;
#pragma unroll
                for (int j = 0; j < 8; j++) {
                    int cl = wn * 64 + j * 8 + (lane & 3) * 2;
                    *reinterpret_cast<float2*>(&prow[cl]) =
                        make_float2(acc[i][j][half * 2 + 0], acc[i][j][half * 2 + 1]);
                }
            }
        }
    }
}

// ============================ combine ============================
__global__ void combine_kernel(float* __restrict__ y) {
    size_t idx = (size_t)blockIdx.x * blockDim.x + threadIdx.x;
    if (idx >= (size_t)T_TOK * DIMN / 4) return;
    int t = (int)(idx / (DIMN / 4));
    int d4 = (int)(idx % (DIMN / 4)) * 4;
    int s0 = g_slot[2 * t], s1 = g_slot[2 * t + 1];
    float w0 = g_wt[s0], w1 = g_wt[s1];
    float4 p0 = *reinterpret_cast<const float4*>(&g_P[(size_t)s0 * DIMN + d4]);
    float4 p1 = *reinterpret_cast<const float4*>(&g_P[(size_t)s1 * DIMN + d4]);
    float4 r;
    r.x = w0 * p0.x + w1 * p1.x;
    r.y = w0 * p0.y + w1 * p1.y;
    r.z = w0 * p0.z + w1 * p1.z;
    r.w = w0 * p0.w + w1 * p1.w;
    *reinterpret_cast<float4*>(&y[(size_t)t * DIMN + d4]) = r;
}

// ============================ launch ============================
extern "C" void kernel_launch(void* const* d_in, const int* in_sizes, int n_in,
                              void* d_out, int out_size) {
    const float* x  = (const float*)d_in[0];
    const float* wg = (const float*)d_in[1];
    const float* w1 = (const float*)d_in[2];
    const float* w2 = (const float*)d_in[3];
    const float* w3 = (const float*)d_in[4];
    float* y = (float*)d_out;

    const int smem1 = NSTG * (128 + 64 + 64) * PADA * 4;      // 61440
    const int smem2 = NSTG * (128 * PADA + 16 * PADB) * 4;    // 56832
    cudaFuncSetAttribute(ffn1_kernel, cudaFuncAttributeMaxDynamicSharedMemorySize, smem1);
    cudaFuncSetAttribute(ffn2_kernel, cudaFuncAttributeMaxDynamicSharedMemorySize, smem2);

    reset_kernel<<<1, 32>>>();
    gate_kernel<<<T_TOK / 8, 256>>>(x, wg);
    scan_kernel<<<1, 32>>>();
    build_kernel<<<T_TOK / 256, 256>>>();
    gather_kernel<<<(int)(((size_t)NA * (DIMN / 4) + 255) / 256), 256>>>(x);
    convw_kernel<<<(int)(((size_t)NE * HIDN * DIMN / 4 + 255) / 256), 256>>>(w1, w2, w3);
    ffn1_kernel<<<dim3(HIDN / 64, 128, NE), 256, smem1>>>();
    ffn2_kernel<<<dim3(DIMN / 128, 128, NE), 256, smem2>>>();
    combine_kernel<<<(T_TOK * DIMN / 4 + 255) / 256, 256>>>(y);
}